// round 9
// baseline (speedup 1.0000x reference)
#include <cuda_runtime.h>
#include <cuda_bf16.h>
#include <cuda_fp16.h>
#include <math.h>
#include <stdint.h>

#define NR 2048      // batch*tlen rows
#define DK 1024      // input dim
#define VO 32000     // vocab
#define SL 512       // slen
#define NB 32        // batch
#define CV 500       // copy vocab
#define OC 32500     // output cols

#define HSCALE 8.0f
#define WSCALE 128.0f
#define DESCALE (1.0f / 1024.0f)   // exact 2^-10

#define NMMA 208                   // col-blocks on mma path; rest on SIMT half2 path

// ---------------- scratch (device globals) ----------------
static __device__ __nv_bfloat16 g_Mx[(size_t)NR * VO];          // 131 MB logits (pre-affine)
static __device__ __align__(16) __half g_hid_h[(size_t)NR * DK];    // 4 MB (scaled)
static __device__ __align__(16) __half g_W_h[(size_t)VO * DK];      // 65.5 MB (scaled)
static __device__ float g_xnorm[NR];
static __device__ float g_pcopy[NR];
static __device__ float g_ss[NR];
static __device__ float g_db[NR];
static __device__ float g_y2;

// ---------------- helpers ----------------
__device__ __forceinline__ uint32_t smem_u32(const void* p) {
    uint32_t a;
    asm("{ .reg .u64 t; cvta.to.shared.u64 t, %1; cvt.u32.u64 %0, t; }" : "=r"(a) : "l"(p));
    return a;
}
__device__ __forceinline__ void cp16(uint32_t saddr, const void* g) {
    asm volatile("cp.async.cg.shared.global [%0], [%1], 16;" :: "r"(saddr), "l"(g));
}
__device__ __forceinline__ float block_reduce_sum(float v, float* sbuf) {
    int tid = threadIdx.x;
    sbuf[tid] = v;
    __syncthreads();
    #pragma unroll
    for (int off = 128; off > 0; off >>= 1) {
        if (tid < off) sbuf[tid] += sbuf[tid + off];
        __syncthreads();
    }
    float r = sbuf[0];
    __syncthreads();
    return r;
}

// ---------------- fp16 conversion (scaled) ----------------
__global__ void __launch_bounds__(256) conv_h_kernel(const float* __restrict__ src,
                                                     __half* __restrict__ dst,
                                                     float scale, int n4) {
    int i = blockIdx.x * 256 + threadIdx.x;
    if (i < n4) {
        float4 v = ((const float4*)src)[i];
        __half2 lo = __floats2half2_rn(v.x * scale, v.y * scale);
        __half2 hi = __floats2half2_rn(v.z * scale, v.w * scale);
        ((__half2*)dst)[2 * i]     = lo;
        ((__half2*)dst)[2 * i + 1] = hi;
    }
}

// ---------------- ||b||^2 ----------------
__global__ void __launch_bounds__(256) bnorm_kernel(const float* __restrict__ b) {
    __shared__ float sbuf[256];
    float s = 0.f;
    for (int i = threadIdx.x; i < VO; i += 256) { float v = b[i]; s += v * v; }
    s = block_reduce_sum(s, sbuf);
    if (threadIdx.x == 0) g_y2 = s;
}

// --------- per-row: x_norm, p_copy (full fp32 path) + zero accumulators ---------
__global__ void __launch_bounds__(256) row_prep_kernel(const float* __restrict__ hidden,
                                                       const float* __restrict__ Wc,
                                                       const float* __restrict__ bcp) {
    __shared__ float s1[256];
    __shared__ float s2[256];
    int row = blockIdx.x;
    const float4* h4 = (const float4*)(hidden + (size_t)row * DK);
    const float4* w4 = (const float4*)Wc;
    int i = threadIdx.x;
    float4 h = h4[i];
    float4 w = w4[i];
    float ss = h.x * h.x + h.y * h.y + h.z * h.z + h.w * h.w;
    float sm = h.x * w.x + h.y * w.y + h.z * w.z + h.w * w.w;
    ss = block_reduce_sum(ss, s1);
    sm = block_reduce_sum(sm, s2);
    if (threadIdx.x == 0) {
        g_ss[row] = 0.f;
        g_db[row] = 0.f;
        float xn = fmaxf(sqrtf(ss), 1e-15f);
        g_xnorm[row] = xn;
        float art = atanhf(fminf(xn, 1.f - 1e-7f));
        float mn = fmaxf(fabsf(sm), 1e-15f);
        float t1 = tanhf(mn / xn * art) * (sm / mn);
        float bc = *bcp;
        float y2 = bc * bc, x2 = t1 * t1, xy = t1 * bc;
        float num = (1.f + 2.f * xy + y2) * t1 + (1.f - x2) * bc;
        float den = fmaxf(1.f + 2.f * xy + x2 * y2, 1e-15f);
        float u = num / den;
        float au = fmaxf(fabsf(u), 1e-15f);
        if (au > 0.996f) u = u / au * 0.996f;
        g_pcopy[row] = 1.f / (1.f + expf(-u));
    }
}

// ============ HYBRID GEMM: g_Mx = hidden @ W^T + fused ss/db reductions ============
// blocks bx < NMMA: fp16 mma.sync path (tensor pipe)
// blocks bx >= NMMA: half2 SIMT path (fma pipe) — overlaps with mma CTAs on same SMs
#define BM 128
#define BN 128
#define BK 64
#define NSTG (DK / BK)          // 16 (mma path)
#define STAGE_BYTES 32768
#define SMEM_GEMM (2 * STAGE_BYTES)
#define NST2 (DK / 32)          // 32 (SIMT path, BK=32)
#define S2_STAGE 24576          // As 8KB + Bs2(dup) 16KB

__device__ __forceinline__ uint32_t sw128(uint32_t off) {
    return off ^ ((off >> 3) & 0x70);
}

__global__ void __launch_bounds__(256) gemm_hybrid_kernel(const float* __restrict__ bvec) {
    extern __shared__ char smem[];
    const int tid = threadIdx.x;
    const int row0 = blockIdx.y * BM;
    const int col0 = blockIdx.x * BN;

    if (blockIdx.x < NMMA) {
        // ================= mma.sync path =================
        const uint32_t sb = smem_u32(smem);
        const int wid = tid >> 5;
        const int lane = tid & 31;
        const int warp_m = wid & 1;
        const int warp_n = wid >> 1;
        const int lr = tid >> 3;
        const int lk = tid & 7;

        uint32_t acc[4][4][2];
        #pragma unroll
        for (int a = 0; a < 4; a++)
            #pragma unroll
            for (int b = 0; b < 4; b++) { acc[a][b][0] = 0u; acc[a][b][1] = 0u; }

        {
            const uint32_t abase = sb, bbase = sb + 16384;
            #pragma unroll
            for (int it = 0; it < 4; it++) {
                int r = lr + it * 32;
                uint32_t off = sw128(r * 128 + lk * 16);
                cp16(abase + off, g_hid_h + (size_t)(row0 + r) * DK + lk * 8);
                cp16(bbase + off, g_W_h + (size_t)(col0 + r) * DK + lk * 8);
            }
            asm volatile("cp.async.commit_group;" ::: "memory");
            asm volatile("cp.async.wait_group 0;" ::: "memory");
        }
        __syncthreads();

        for (int ks = 0; ks < NSTG; ks++) {
            if (ks + 1 < NSTG) {
                const uint32_t nb = sb + ((ks + 1) & 1) * STAGE_BYTES;
                const int k0 = (ks + 1) * BK;
                #pragma unroll
                for (int it = 0; it < 4; it++) {
                    int r = lr + it * 32;
                    uint32_t off = sw128(r * 128 + lk * 16);
                    cp16(nb + off, g_hid_h + (size_t)(row0 + r) * DK + k0 + lk * 8);
                    cp16(nb + 16384 + off, g_W_h + (size_t)(col0 + r) * DK + k0 + lk * 8);
                }
                asm volatile("cp.async.commit_group;" ::: "memory");
            }

            const uint32_t abase = sb + (ks & 1) * STAGE_BYTES;
            const uint32_t bbase = abase + 16384;
            #pragma unroll
            for (int kk = 0; kk < 4; kk++) {
                uint32_t afr[4][4];
                uint32_t bfr[4][2];
                #pragma unroll
                for (int mf = 0; mf < 4; mf++) {
                    int r = warp_m * 64 + mf * 16 + (lane & 15);
                    uint32_t off = sw128(r * 128 + kk * 32 + ((lane >> 4) & 1) * 16);
                    asm volatile("ldmatrix.sync.aligned.m8n8.x4.shared.b16 {%0,%1,%2,%3}, [%4];"
                                 : "=r"(afr[mf][0]), "=r"(afr[mf][1]),
                                   "=r"(afr[mf][2]), "=r"(afr[mf][3])
                                 : "r"(abase + off));
                }
                #pragma unroll
                for (int nh = 0; nh < 2; nh++) {
                    int r = warp_n * 32 + nh * 16 + ((lane >> 4) & 1) * 8 + (lane & 7);
                    uint32_t off = sw128(r * 128 + kk * 32 + ((lane >> 3) & 1) * 16);
                    asm volatile("ldmatrix.sync.aligned.m8n8.x4.shared.b16 {%0,%1,%2,%3}, [%4];"
                                 : "=r"(bfr[nh * 2][0]), "=r"(bfr[nh * 2][1]),
                                   "=r"(bfr[nh * 2 + 1][0]), "=r"(bfr[nh * 2 + 1][1])
                                 : "r"(bbase + off));
                }
                #pragma unroll
                for (int mf = 0; mf < 4; mf++)
                    #pragma unroll
                    for (int nf = 0; nf < 4; nf++) {
                        asm volatile(
                            "mma.sync.aligned.m16n8k16.row.col.f16.f16.f16.f16 "
                            "{%0,%1}, {%2,%3,%4,%5}, {%6,%7}, {%0,%1};"
                            : "+r"(acc[mf][nf][0]), "+r"(acc[mf][nf][1])
                            : "r"(afr[mf][0]), "r"(afr[mf][1]),
                              "r"(afr[mf][2]), "r"(afr[mf][3]),
                              "r"(bfr[nf][0]), "r"(bfr[nf][1]));
                    }
            }
            if (ks + 1 < NSTG)
                asm volatile("cp.async.wait_group 0;" ::: "memory");
            __syncthreads();
        }

        // ---- epilogue ----
        float bb[4][2];
        #pragma unroll
        for (int nf = 0; nf < 4; nf++) {
            int c = col0 + warp_n * 32 + nf * 8 + (lane & 3) * 2;
            float2 v = *(const float2*)(bvec + c);
            bb[nf][0] = v.x; bb[nf][1] = v.y;
        }
        #pragma unroll
        for (int mf = 0; mf < 4; mf++) {
            #pragma unroll
            for (int hf = 0; hf < 2; hf++) {
                int row = row0 + warp_m * 64 + mf * 16 + (lane >> 2) + hf * 8;
                __nv_bfloat16* orow = g_Mx + (size_t)row * VO + col0 + warp_n * 32 + (lane & 3) * 2;
                float ss = 0.f, db = 0.f;
                #pragma unroll
                for (int nf = 0; nf < 4; nf++) {
                    float2 cv = __half22float2(*(__half2*)&acc[mf][nf][hf]);
                    float c0 = cv.x * DESCALE;
                    float c1 = cv.y * DESCALE;
                    ss += c0 * c0 + c1 * c1;
                    db += c0 * bb[nf][0] + c1 * bb[nf][1];
                    *(__nv_bfloat162*)(orow + nf * 8) = __floats2bfloat162_rn(c0, c1);
                }
                ss += __shfl_xor_sync(0xffffffff, ss, 1);
                ss += __shfl_xor_sync(0xffffffff, ss, 2);
                db += __shfl_xor_sync(0xffffffff, db, 1);
                db += __shfl_xor_sync(0xffffffff, db, 2);
                if ((lane & 3) == 0) {
                    atomicAdd(&g_ss[row], ss);
                    atomicAdd(&g_db[row], db);
                }
            }
        }
    } else {
        // ================= half2 SIMT path (fma pipe) =================
        // thread: tx = col group (8 cols), ty = row group (8 rows)
        const int tx = tid & 15;
        const int ty = tid >> 4;
        __half2 acc[4][8];
        #pragma unroll
        for (int rp = 0; rp < 4; rp++)
            #pragma unroll
            for (int c = 0; c < 8; c++) acc[rp][c] = __floats2half2_rn(0.f, 0.f);

        union U { uint4 u; __half h[8]; };
        U ar[2], br[2];

        // per-thread load coords: 2 chunks each for A,B: id = tid + it*256
        // r = id>>2 (0..127), kg = id&3 (8-half group)
        auto ldg_stage = [&](int ks) {
            #pragma unroll
            for (int it = 0; it < 2; it++) {
                int id = tid + it * 256;
                int r = id >> 2, kg = id & 3;
                ar[it].u = *(const uint4*)(g_hid_h + (size_t)(row0 + r) * DK + ks * 32 + kg * 8);
                br[it].u = *(const uint4*)(g_W_h + (size_t)(col0 + r) * DK + ks * 32 + kg * 8);
            }
        };
        auto sts_stage = [&](int buf) {
            char* base = smem + buf * S2_STAGE;
            #pragma unroll
            for (int it = 0; it < 2; it++) {
                int id = tid + it * 256;
                int r = id >> 2, kg = id & 3;
                #pragma unroll
                for (int j = 0; j < 8; j++) {
                    *(__half*)(base + (kg * 8 + j) * 256 + r * 2) = ar[it].h[j];
                    *(__half2*)(base + 8192 + (kg * 8 + j) * 512 + r * 4) =
                        __half2half2(br[it].h[j]);
                }
            }
        };

        ldg_stage(0);
        sts_stage(0);
        __syncthreads();

        for (int ks = 0; ks < NST2; ks++) {
            if (ks + 1 < NST2) ldg_stage(ks + 1);
            const char* As = smem + (ks & 1) * S2_STAGE;
            const char* Bs = As + 8192;
            #pragma unroll 8
            for (int k = 0; k < 32; k++) {
                U av; av.u = *(const uint4*)(As + k * 256 + ty * 16);
                U bv0; bv0.u = *(const uint4*)(Bs + k * 512 + tx * 32);
                U bv1; bv1.u = *(const uint4*)(Bs + k * 512 + tx * 32 + 16);
                const __half2* a2 = (const __half2*)av.h;
                const __half2* b2lo = (const __half2*)bv0.h;
                const __half2* b2hi = (const __half2*)bv1.h;
                #pragma unroll
                for (int rp = 0; rp < 4; rp++) {
                    #pragma unroll
                    for (int c = 0; c < 4; c++) {
                        acc[rp][c] = __hfma2(a2[rp], b2lo[c], acc[rp][c]);
                        acc[rp][c + 4] = __hfma2(a2[rp], b2hi[c], acc[rp][c + 4]);
                    }
                }
            }
            if (ks + 1 < NST2) {
                sts_stage((ks + 1) & 1);
                __syncthreads();
            }
        }

        // ---- epilogue: descale, write Mx bf16, fused ss/db reductions ----
        float bvv[8];
        #pragma unroll
        for (int c = 0; c < 8; c += 4)
            *(float4*)&bvv[c] = *(const float4*)(bvec + col0 + tx * 8 + c);

        #pragma unroll
        for (int rp = 0; rp < 4; rp++) {
            #pragma unroll
            for (int h = 0; h < 2; h++) {
                int row = row0 + ty * 8 + rp * 2 + h;
                float v[8];
                #pragma unroll
                for (int c = 0; c < 8; c++)
                    v[c] = (h == 0 ? __low2float(acc[rp][c]) : __high2float(acc[rp][c])) * DESCALE;
                float ss = 0.f, db = 0.f;
                #pragma unroll
                for (int c = 0; c < 8; c++) { ss += v[c] * v[c]; db += v[c] * bvv[c]; }
                __nv_bfloat16* orow = g_Mx + (size_t)row * VO + col0 + tx * 8;
                #pragma unroll
                for (int c = 0; c < 8; c += 2)
                    *(__nv_bfloat162*)(orow + c) = __floats2bfloat162_rn(v[c], v[c + 1]);
                ss += __shfl_xor_sync(0xffffffff, ss, 1);
                ss += __shfl_xor_sync(0xffffffff, ss, 2);
                ss += __shfl_xor_sync(0xffffffff, ss, 4);
                ss += __shfl_xor_sync(0xffffffff, ss, 8);
                db += __shfl_xor_sync(0xffffffff, db, 1);
                db += __shfl_xor_sync(0xffffffff, db, 2);
                db += __shfl_xor_sync(0xffffffff, db, 4);
                db += __shfl_xor_sync(0xffffffff, db, 8);
                if (tx == 0) {
                    atomicAdd(&g_ss[row], ss);
                    atomicAdd(&g_db[row], db);
                }
            }
        }
    }
}

// ====== fused output: scalar chain + exact softmax (no max needed: |l|<=0.996) ======
__global__ void __launch_bounds__(256) fused_out_kernel(const float* __restrict__ b,
                                                        const int* __restrict__ padp,
                                                        float* __restrict__ out) {
    extern __shared__ char smraw[];
    __nv_bfloat162* smx = (__nv_bfloat162*)smraw;
    __shared__ float rbuf[256];
    __shared__ float sc_g, sc_d, sc_inv0;

    const int row = blockIdx.x;
    const int tid = threadIdx.x;
    const int pad = *padp;

    const uint4* src = (const uint4*)(g_Mx + (size_t)row * VO);
    uint4* dst = (uint4*)smraw;
    #pragma unroll 4
    for (int i = tid; i < VO / 8; i += 256) dst[i] = src[i];

    if (tid == 0) {
        float ss = g_ss[row];
        float db = g_db[row];
        float xn = g_xnorm[row];
        float mxn = fmaxf(sqrtf(ss), 1e-15f);
        float art = atanhf(fminf(xn, 1.f - 1e-7f));
        float t = tanhf(mxn / xn * art);
        float alpha = t / mxn;
        float xy = alpha * db;
        float x2 = t * t;
        float y2 = g_y2;
        float Ac = 1.f + 2.f * xy + y2;
        float Bc = 1.f - x2;
        float den = fmaxf(1.f + 2.f * xy + x2 * y2, 1e-15f);
        float nl2 = (Ac * Ac * t * t + 2.f * Ac * Bc * alpha * db + Bc * Bc * y2) / (den * den);
        float nl = fmaxf(sqrtf(nl2), 1e-15f);
        float sc = (nl > 0.996f) ? (0.996f / nl) : 1.f;
        sc_g = sc * Ac * alpha / den;
        sc_d = sc * Bc / den;
        sc_inv0 = 1.f - g_pcopy[row];
    }
    __syncthreads();

    const float gamma = sc_g, delta = sc_d;
    const float2* b2 = (const float2*)b;

    float s = 0.f;
    for (int i = tid; i < VO / 2; i += 256) {
        __nv_bfloat162 m = smx[i];
        float2 bv = b2[i];
        float l0 = gamma * __bfloat162float(m.x) + delta * bv.x;
        float l1 = gamma * __bfloat162float(m.y) + delta * bv.y;
        float e0 = __expf(l0);
        float e1 = __expf(l1);
        int base = i * 2;
        if (pad == base) e0 = 0.f;
        if (pad == base + 1) e1 = 0.f;
        s += e0 + e1;
    }
    s = block_reduce_sum(s, rbuf);
    const float inv = sc_inv0 / s;

    float2* o2 = (float2*)(out + (size_t)row * OC);
    for (int i = tid; i < VO / 2; i += 256) {
        __nv_bfloat162 m = smx[i];
        float2 bv = b2[i];
        float l0 = gamma * __bfloat162float(m.x) + delta * bv.x;
        float l1 = gamma * __bfloat162float(m.y) + delta * bv.y;
        float2 r;
        r.x = __expf(l0) * inv;
        r.y = __expf(l1) * inv;
        int base = i * 2;
        if (pad == base) r.x = 0.f;
        if (pad == base + 1) r.y = 0.f;
        o2[i] = r;
    }
}

// ------- copy branch: per-batch (64x512)@(512x500) small GEMM (full fp32) -------
#define SCH 32
__global__ void __launch_bounds__(256) copy_kernel(const float* __restrict__ attn,
                                                   const float* __restrict__ src,
                                                   float* __restrict__ out) {
    __shared__ float sa[64][SCH + 1];
    __shared__ float sbuf[SCH][128];
    __shared__ float spc[64];
    const int bb = blockIdx.y;
    const int c0 = blockIdx.x * 128;
    const int tid = threadIdx.x;
    const int tx = tid % 16;
    const int ty = tid / 16;

    if (tid < 64) spc[tid] = g_pcopy[tid * NB + bb];

    float acc[4][8] = {};
    for (int s0 = 0; s0 < SL; s0 += SCH) {
        __syncthreads();
        for (int i = tid; i < 64 * (SCH / 4); i += 256) {
            int t = i / (SCH / 4);
            int sv = i % (SCH / 4);
            float4 v = *(const float4*)(attn + (size_t)(t * NB + bb) * SL + s0 + sv * 4);
            float pc = spc[t];
            sa[t][sv * 4 + 0] = v.x * pc;
            sa[t][sv * 4 + 1] = v.y * pc;
            sa[t][sv * 4 + 2] = v.z * pc;
            sa[t][sv * 4 + 3] = v.w * pc;
        }
        for (int i = tid; i < SCH * 128; i += 256) {
            int s = i / 128;
            int c = i % 128;
            int cg = c0 + c;
            sbuf[s][c] = (cg < CV) ? src[(size_t)(s0 + s) * (NB * CV) + bb * CV + cg] : 0.f;
        }
        __syncthreads();
        #pragma unroll 8
        for (int s = 0; s < SCH; s++) {
            float a[4], bf[8];
            #pragma unroll
            for (int i = 0; i < 4; i++) a[i] = sa[ty * 4 + i][s];
            #pragma unroll
            for (int j = 0; j < 8; j++) bf[j] = sbuf[s][tx * 8 + j];
            #pragma unroll
            for (int i = 0; i < 4; i++)
                #pragma unroll
                for (int j = 0; j < 8; j++)
                    acc[i][j] = fmaf(a[i], bf[j], acc[i][j]);
        }
    }
    #pragma unroll
    for (int i = 0; i < 4; i++) {
        int t = ty * 4 + i;
        #pragma unroll
        for (int j = 0; j < 8; j++) {
            int c = c0 + tx * 8 + j;
            if (c < CV)
                out[(size_t)(t * NB + bb) * OC + VO + c] = acc[i][j];
        }
    }
}

// ---------------- launch ----------------
extern "C" void kernel_launch(void* const* d_in, const int* in_sizes, int n_in,
                              void* d_out, int out_size) {
    const float* hidden = (const float*)d_in[0];
    const float* attn   = (const float*)d_in[1];
    const float* srcm   = (const float*)d_in[2];
    const float* W      = (const float*)d_in[3];
    const float* b      = (const float*)d_in[4];
    const float* Wc     = (const float*)d_in[5];
    const float* bc     = (const float*)d_in[6];
    const int*   pad    = (const int*)d_in[7];
    float* out = (float*)d_out;

    cudaFuncSetAttribute(gemm_hybrid_kernel,
                         cudaFuncAttributeMaxDynamicSharedMemorySize, SMEM_GEMM);
    cudaFuncSetAttribute(fused_out_kernel,
                         cudaFuncAttributeMaxDynamicSharedMemorySize, VO * 2);

    __half* hid_h;
    __half* W_h;
    cudaGetSymbolAddress((void**)&hid_h, g_hid_h);
    cudaGetSymbolAddress((void**)&W_h, g_W_h);

    conv_h_kernel<<<(NR * DK / 4 + 255) / 256, 256>>>(hidden, hid_h, HSCALE, NR * DK / 4);
    conv_h_kernel<<<(VO * DK / 4 + 255) / 256, 256>>>(W, W_h, WSCALE, VO * DK / 4);
    bnorm_kernel<<<1, 256>>>(b);
    row_prep_kernel<<<NR, 256>>>(hidden, Wc, bc);
    gemm_hybrid_kernel<<<dim3(VO / BN, NR / BM), 256, SMEM_GEMM>>>(b);
    fused_out_kernel<<<NR, 256, VO * 2>>>(b, pad, out);
    copy_kernel<<<dim3((CV + 127) / 128, NB), 256>>>(attn, srcm, out);
}

// round 10
// speedup vs baseline: 1.8409x; 1.8409x over previous
#include <cuda_runtime.h>
#include <cuda_bf16.h>
#include <cuda_fp16.h>
#include <math.h>
#include <stdint.h>

#define NR 2048      // batch*tlen rows
#define DK 1024      // input dim
#define VO 32000     // vocab
#define SL 512       // slen
#define NB 32        // batch
#define CV 500       // copy vocab
#define OC 32500     // output cols

#define HSCALE 8.0f
#define WSCALE 128.0f
#define DESCALE (1.0f / 1024.0f)   // exact 2^-10

// ---------------- scratch (device globals) ----------------
static __device__ __nv_bfloat16 g_Mx[(size_t)NR * VO];          // 131 MB logits (pre-affine)
static __device__ __align__(16) __half g_hid_h[(size_t)NR * DK];    // 4 MB (scaled)
static __device__ __align__(16) __half g_W_h[(size_t)VO * DK];      // 65.5 MB (scaled)
static __device__ float g_xnorm[NR];
static __device__ float g_pcopy[NR];
static __device__ float g_ss[NR];
static __device__ float g_db[NR];
static __device__ float g_y2;

// ---------------- helpers ----------------
__device__ __forceinline__ uint32_t smem_u32(const void* p) {
    uint32_t a;
    asm("{ .reg .u64 t; cvta.to.shared.u64 t, %1; cvt.u32.u64 %0, t; }" : "=r"(a) : "l"(p));
    return a;
}
__device__ __forceinline__ void cp16(uint32_t saddr, const void* g) {
    asm volatile("cp.async.cg.shared.global [%0], [%1], 16;" :: "r"(saddr), "l"(g));
}
__device__ __forceinline__ float block_reduce_sum(float v, float* sbuf) {
    int tid = threadIdx.x;
    sbuf[tid] = v;
    __syncthreads();
    #pragma unroll
    for (int off = 128; off > 0; off >>= 1) {
        if (tid < off) sbuf[tid] += sbuf[tid + off];
        __syncthreads();
    }
    float r = sbuf[0];
    __syncthreads();
    return r;
}

// ------- W fp32 -> fp16 (scaled); last block computes ||b||^2 -------
#define WCONV_BLOCKS ((VO * DK / 4 + 255) / 256)
__global__ void __launch_bounds__(256) convW_bnorm_kernel(const float* __restrict__ W,
                                                          __half* __restrict__ dst,
                                                          const float* __restrict__ b) {
    if (blockIdx.x == WCONV_BLOCKS) {
        __shared__ float sbuf[256];
        float s = 0.f;
        for (int i = threadIdx.x; i < VO; i += 256) { float v = b[i]; s += v * v; }
        s = block_reduce_sum(s, sbuf);
        if (threadIdx.x == 0) g_y2 = s;
        return;
    }
    int i = blockIdx.x * 256 + threadIdx.x;
    if (i < VO * DK / 4) {
        float4 v = ((const float4*)W)[i];
        __half2 lo = __floats2half2_rn(v.x * WSCALE, v.y * WSCALE);
        __half2 hi = __floats2half2_rn(v.z * WSCALE, v.w * WSCALE);
        ((__half2*)dst)[2 * i]     = lo;
        ((__half2*)dst)[2 * i + 1] = hi;
    }
}

// ---- per-row: hidden->fp16 conversion, x_norm, p_copy, zero accumulators ----
__global__ void __launch_bounds__(256) row_prep_kernel(const float* __restrict__ hidden,
                                                       const float* __restrict__ Wc,
                                                       const float* __restrict__ bcp,
                                                       __half* __restrict__ hid_h) {
    __shared__ float s1[256];
    __shared__ float s2[256];
    int row = blockIdx.x;
    const float4* h4 = (const float4*)(hidden + (size_t)row * DK);
    const float4* w4 = (const float4*)Wc;
    int i = threadIdx.x;
    float4 h = h4[i];
    float4 w = w4[i];
    // fused scaled fp16 conversion of hidden
    __half2 lo = __floats2half2_rn(h.x * HSCALE, h.y * HSCALE);
    __half2 hi = __floats2half2_rn(h.z * HSCALE, h.w * HSCALE);
    ((__half2*)(hid_h + (size_t)row * DK))[2 * i]     = lo;
    ((__half2*)(hid_h + (size_t)row * DK))[2 * i + 1] = hi;

    float ss = h.x * h.x + h.y * h.y + h.z * h.z + h.w * h.w;
    float sm = h.x * w.x + h.y * w.y + h.z * w.z + h.w * w.w;
    ss = block_reduce_sum(ss, s1);
    sm = block_reduce_sum(sm, s2);
    if (threadIdx.x == 0) {
        g_ss[row] = 0.f;
        g_db[row] = 0.f;
        float xn = fmaxf(sqrtf(ss), 1e-15f);
        g_xnorm[row] = xn;
        float art = atanhf(fminf(xn, 1.f - 1e-7f));
        float mn = fmaxf(fabsf(sm), 1e-15f);
        float t1 = tanhf(mn / xn * art) * (sm / mn);
        float bc = *bcp;
        float y2 = bc * bc, x2 = t1 * t1, xy = t1 * bc;
        float num = (1.f + 2.f * xy + y2) * t1 + (1.f - x2) * bc;
        float den = fmaxf(1.f + 2.f * xy + x2 * y2, 1e-15f);
        float u = num / den;
        float au = fmaxf(fabsf(u), 1e-15f);
        if (au > 0.996f) u = u / au * 0.996f;
        g_pcopy[row] = 1.f / (1.f + expf(-u));
    }
}

// ============ fp16 mma.sync GEMM (f16 accumulate): g_Mx = hidden @ W^T ============
// CTA tile 128x128, BK=64, double-buffered cp.async, 8 warps (2m x 4n), warp 64x32.
#define BM 128
#define BN 128
#define BK 64
#define NSTG (DK / BK)          // 16
#define STAGE_BYTES 32768
#define SMEM_GEMM (2 * STAGE_BYTES)

__device__ __forceinline__ uint32_t sw128(uint32_t off) {
    return off ^ ((off >> 3) & 0x70);
}

__global__ void __launch_bounds__(256) gemm_mma_kernel(const float* __restrict__ bvec) {
    extern __shared__ char smem[];
    const uint32_t sb = smem_u32(smem);
    const int tid = threadIdx.x;
    const int wid = tid >> 5;
    const int lane = tid & 31;
    const int warp_m = wid & 1;
    const int warp_n = wid >> 1;
    const int row0 = blockIdx.y * BM;
    const int col0 = blockIdx.x * BN;

    const int lr = tid >> 3;
    const int lk = tid & 7;

    uint32_t acc[4][4][2];       // f16x2 accumulators
    #pragma unroll
    for (int a = 0; a < 4; a++)
        #pragma unroll
        for (int b = 0; b < 4; b++) { acc[a][b][0] = 0u; acc[a][b][1] = 0u; }

    {
        const uint32_t abase = sb, bbase = sb + 16384;
        #pragma unroll
        for (int it = 0; it < 4; it++) {
            int r = lr + it * 32;
            uint32_t off = sw128(r * 128 + lk * 16);
            cp16(abase + off, g_hid_h + (size_t)(row0 + r) * DK + lk * 8);
            cp16(bbase + off, g_W_h + (size_t)(col0 + r) * DK + lk * 8);
        }
        asm volatile("cp.async.commit_group;" ::: "memory");
        asm volatile("cp.async.wait_group 0;" ::: "memory");
    }
    __syncthreads();

    for (int ks = 0; ks < NSTG; ks++) {
        if (ks + 1 < NSTG) {
            const uint32_t nb = sb + ((ks + 1) & 1) * STAGE_BYTES;
            const int k0 = (ks + 1) * BK;
            #pragma unroll
            for (int it = 0; it < 4; it++) {
                int r = lr + it * 32;
                uint32_t off = sw128(r * 128 + lk * 16);
                cp16(nb + off, g_hid_h + (size_t)(row0 + r) * DK + k0 + lk * 8);
                cp16(nb + 16384 + off, g_W_h + (size_t)(col0 + r) * DK + k0 + lk * 8);
            }
            asm volatile("cp.async.commit_group;" ::: "memory");
        }

        const uint32_t abase = sb + (ks & 1) * STAGE_BYTES;
        const uint32_t bbase = abase + 16384;
        #pragma unroll
        for (int kk = 0; kk < 4; kk++) {
            uint32_t afr[4][4];
            uint32_t bfr[4][2];
            #pragma unroll
            for (int mf = 0; mf < 4; mf++) {
                int r = warp_m * 64 + mf * 16 + (lane & 15);
                uint32_t off = sw128(r * 128 + kk * 32 + ((lane >> 4) & 1) * 16);
                asm volatile("ldmatrix.sync.aligned.m8n8.x4.shared.b16 {%0,%1,%2,%3}, [%4];"
                             : "=r"(afr[mf][0]), "=r"(afr[mf][1]),
                               "=r"(afr[mf][2]), "=r"(afr[mf][3])
                             : "r"(abase + off));
            }
            #pragma unroll
            for (int nh = 0; nh < 2; nh++) {
                int r = warp_n * 32 + nh * 16 + ((lane >> 4) & 1) * 8 + (lane & 7);
                uint32_t off = sw128(r * 128 + kk * 32 + ((lane >> 3) & 1) * 16);
                asm volatile("ldmatrix.sync.aligned.m8n8.x4.shared.b16 {%0,%1,%2,%3}, [%4];"
                             : "=r"(bfr[nh * 2][0]), "=r"(bfr[nh * 2][1]),
                               "=r"(bfr[nh * 2 + 1][0]), "=r"(bfr[nh * 2 + 1][1])
                             : "r"(bbase + off));
            }
            #pragma unroll
            for (int mf = 0; mf < 4; mf++)
                #pragma unroll
                for (int nf = 0; nf < 4; nf++) {
                    asm volatile(
                        "mma.sync.aligned.m16n8k16.row.col.f16.f16.f16.f16 "
                        "{%0,%1}, {%2,%3,%4,%5}, {%6,%7}, {%0,%1};"
                        : "+r"(acc[mf][nf][0]), "+r"(acc[mf][nf][1])
                        : "r"(afr[mf][0]), "r"(afr[mf][1]),
                          "r"(afr[mf][2]), "r"(afr[mf][3]),
                          "r"(bfr[nf][0]), "r"(bfr[nf][1]));
                }
        }
        if (ks + 1 < NSTG)
            asm volatile("cp.async.wait_group 0;" ::: "memory");
        __syncthreads();
    }

    // ---- epilogue: descale, write Mx bf16, fused ss/db row reductions ----
    float bb[4][2];
    #pragma unroll
    for (int nf = 0; nf < 4; nf++) {
        int c = col0 + warp_n * 32 + nf * 8 + (lane & 3) * 2;
        float2 v = *(const float2*)(bvec + c);
        bb[nf][0] = v.x; bb[nf][1] = v.y;
    }
    #pragma unroll
    for (int mf = 0; mf < 4; mf++) {
        #pragma unroll
        for (int hf = 0; hf < 2; hf++) {
            int row = row0 + warp_m * 64 + mf * 16 + (lane >> 2) + hf * 8;
            __nv_bfloat16* orow = g_Mx + (size_t)row * VO + col0 + warp_n * 32 + (lane & 3) * 2;
            float ss = 0.f, db = 0.f;
            #pragma unroll
            for (int nf = 0; nf < 4; nf++) {
                float2 cv = __half22float2(*(__half2*)&acc[mf][nf][hf]);
                float c0 = cv.x * DESCALE;
                float c1 = cv.y * DESCALE;
                ss += c0 * c0 + c1 * c1;
                db += c0 * bb[nf][0] + c1 * bb[nf][1];
                *(__nv_bfloat162*)(orow + nf * 8) = __floats2bfloat162_rn(c0, c1);
            }
            ss += __shfl_xor_sync(0xffffffff, ss, 1);
            ss += __shfl_xor_sync(0xffffffff, ss, 2);
            db += __shfl_xor_sync(0xffffffff, db, 1);
            db += __shfl_xor_sync(0xffffffff, db, 2);
            if ((lane & 3) == 0) {
                atomicAdd(&g_ss[row], ss);
                atomicAdd(&g_db[row], db);
            }
        }
    }
}

// ====== fused output: scalar chain + exact softmax (no max needed: |l|<=0.996) ======
__global__ void __launch_bounds__(256) fused_out_kernel(const float* __restrict__ b,
                                                        const int* __restrict__ padp,
                                                        float* __restrict__ out) {
    extern __shared__ char smraw[];
    __nv_bfloat162* smx = (__nv_bfloat162*)smraw;
    __shared__ float rbuf[256];
    __shared__ float sc_g, sc_d, sc_inv0;

    const int row = blockIdx.x;
    const int tid = threadIdx.x;
    const int pad = *padp;

    const uint4* src = (const uint4*)(g_Mx + (size_t)row * VO);
    uint4* dst = (uint4*)smraw;
    #pragma unroll 4
    for (int i = tid; i < VO / 8; i += 256) dst[i] = src[i];

    if (tid == 0) {
        float ss = g_ss[row];
        float db = g_db[row];
        float xn = g_xnorm[row];
        float mxn = fmaxf(sqrtf(ss), 1e-15f);
        float art = atanhf(fminf(xn, 1.f - 1e-7f));
        float t = tanhf(mxn / xn * art);
        float alpha = t / mxn;
        float xy = alpha * db;
        float x2 = t * t;
        float y2 = g_y2;
        float Ac = 1.f + 2.f * xy + y2;
        float Bc = 1.f - x2;
        float den = fmaxf(1.f + 2.f * xy + x2 * y2, 1e-15f);
        float nl2 = (Ac * Ac * t * t + 2.f * Ac * Bc * alpha * db + Bc * Bc * y2) / (den * den);
        float nl = fmaxf(sqrtf(nl2), 1e-15f);
        float sc = (nl > 0.996f) ? (0.996f / nl) : 1.f;
        sc_g = sc * Ac * alpha / den;
        sc_d = sc * Bc / den;
        sc_inv0 = 1.f - g_pcopy[row];
    }
    __syncthreads();

    const float gamma = sc_g, delta = sc_d;
    const float2* b2 = (const float2*)b;

    float s = 0.f;
    for (int i = tid; i < VO / 2; i += 256) {
        __nv_bfloat162 m = smx[i];
        float2 bv = b2[i];
        float l0 = gamma * __bfloat162float(m.x) + delta * bv.x;
        float l1 = gamma * __bfloat162float(m.y) + delta * bv.y;
        float e0 = __expf(l0);
        float e1 = __expf(l1);
        int base = i * 2;
        if (pad == base) e0 = 0.f;
        if (pad == base + 1) e1 = 0.f;
        s += e0 + e1;
    }
    s = block_reduce_sum(s, rbuf);
    const float inv = sc_inv0 / s;

    float2* o2 = (float2*)(out + (size_t)row * OC);
    for (int i = tid; i < VO / 2; i += 256) {
        __nv_bfloat162 m = smx[i];
        float2 bv = b2[i];
        float l0 = gamma * __bfloat162float(m.x) + delta * bv.x;
        float l1 = gamma * __bfloat162float(m.y) + delta * bv.y;
        float2 r;
        r.x = __expf(l0) * inv;
        r.y = __expf(l1) * inv;
        int base = i * 2;
        if (pad == base) r.x = 0.f;
        if (pad == base + 1) r.y = 0.f;
        o2[i] = r;
    }
}

// ------- copy branch: per-batch (64x512)@(512x500) small GEMM (full fp32) -------
#define SCH 32
__global__ void __launch_bounds__(256) copy_kernel(const float* __restrict__ attn,
                                                   const float* __restrict__ src,
                                                   float* __restrict__ out) {
    __shared__ float sa[64][SCH + 1];
    __shared__ float sbuf[SCH][128];
    __shared__ float spc[64];
    const int bb = blockIdx.y;
    const int c0 = blockIdx.x * 128;
    const int tid = threadIdx.x;
    const int tx = tid % 16;
    const int ty = tid / 16;

    if (tid < 64) spc[tid] = g_pcopy[tid * NB + bb];

    float acc[4][8] = {};
    for (int s0 = 0; s0 < SL; s0 += SCH) {
        __syncthreads();
        for (int i = tid; i < 64 * (SCH / 4); i += 256) {
            int t = i / (SCH / 4);
            int sv = i % (SCH / 4);
            float4 v = *(const float4*)(attn + (size_t)(t * NB + bb) * SL + s0 + sv * 4);
            float pc = spc[t];
            sa[t][sv * 4 + 0] = v.x * pc;
            sa[t][sv * 4 + 1] = v.y * pc;
            sa[t][sv * 4 + 2] = v.z * pc;
            sa[t][sv * 4 + 3] = v.w * pc;
        }
        for (int i = tid; i < SCH * 128; i += 256) {
            int s = i / 128;
            int c = i % 128;
            int cg = c0 + c;
            sbuf[s][c] = (cg < CV) ? src[(size_t)(s0 + s) * (NB * CV) + bb * CV + cg] : 0.f;
        }
        __syncthreads();
        #pragma unroll 8
        for (int s = 0; s < SCH; s++) {
            float a[4], bf[8];
            #pragma unroll
            for (int i = 0; i < 4; i++) a[i] = sa[ty * 4 + i][s];
            #pragma unroll
            for (int j = 0; j < 8; j++) bf[j] = sbuf[s][tx * 8 + j];
            #pragma unroll
            for (int i = 0; i < 4; i++)
                #pragma unroll
                for (int j = 0; j < 8; j++)
                    acc[i][j] = fmaf(a[i], bf[j], acc[i][j]);
        }
    }
    #pragma unroll
    for (int i = 0; i < 4; i++) {
        int t = ty * 4 + i;
        #pragma unroll
        for (int j = 0; j < 8; j++) {
            int c = c0 + tx * 8 + j;
            if (c < CV)
                out[(size_t)(t * NB + bb) * OC + VO + c] = acc[i][j];
        }
    }
}

// ---------------- launch ----------------
extern "C" void kernel_launch(void* const* d_in, const int* in_sizes, int n_in,
                              void* d_out, int out_size) {
    const float* hidden = (const float*)d_in[0];
    const float* attn   = (const float*)d_in[1];
    const float* srcm   = (const float*)d_in[2];
    const float* W      = (const float*)d_in[3];
    const float* b      = (const float*)d_in[4];
    const float* Wc     = (const float*)d_in[5];
    const float* bc     = (const float*)d_in[6];
    const int*   pad    = (const int*)d_in[7];
    float* out = (float*)d_out;

    cudaFuncSetAttribute(gemm_mma_kernel,
                         cudaFuncAttributeMaxDynamicSharedMemorySize, SMEM_GEMM);
    cudaFuncSetAttribute(fused_out_kernel,
                         cudaFuncAttributeMaxDynamicSharedMemorySize, VO * 2);

    __half* hid_h;
    __half* W_h;
    cudaGetSymbolAddress((void**)&hid_h, g_hid_h);
    cudaGetSymbolAddress((void**)&W_h, g_W_h);

    convW_bnorm_kernel<<<WCONV_BLOCKS + 1, 256>>>(W, W_h, b);
    row_prep_kernel<<<NR, 256>>>(hidden, Wc, bc, hid_h);
    gemm_mma_kernel<<<dim3(VO / BN, NR / BM), 256, SMEM_GEMM>>>(b);
    fused_out_kernel<<<NR, 256, VO * 2>>>(b, pad, out);
    copy_kernel<<<dim3((CV + 127) / 128, NB), 256>>>(attn, srcm, out);
}

// round 11
// speedup vs baseline: 1.9029x; 1.0337x over previous
#include <cuda_runtime.h>
#include <cuda_bf16.h>
#include <cuda_fp16.h>
#include <math.h>
#include <stdint.h>

#define NR 2048      // batch*tlen rows
#define DK 1024      // input dim
#define VO 32000     // vocab
#define SL 512       // slen
#define NB 32        // batch
#define CV 500       // copy vocab
#define OC 32500     // output cols

#define HSCALE 8.0f
#define WSCALE 128.0f
#define DESCALE (1.0f / 1024.0f)   // exact 2^-10

// ---------------- scratch (device globals) ----------------
static __device__ __nv_bfloat16 g_Mx[(size_t)NR * VO];          // 131 MB logits (pre-affine)
static __device__ __align__(16) __half g_hid_h[(size_t)NR * DK];    // 4 MB (scaled)
static __device__ __align__(16) __half g_W_h[(size_t)VO * DK];      // 65.5 MB (scaled)
static __device__ float g_xnorm[NR];
static __device__ float g_pcopy[NR];
static __device__ float g_ss[NR];
static __device__ float g_db[NR];
static __device__ float g_y2;

// ---------------- helpers ----------------
__device__ __forceinline__ uint32_t smem_u32(const void* p) {
    uint32_t a;
    asm("{ .reg .u64 t; cvta.to.shared.u64 t, %1; cvt.u32.u64 %0, t; }" : "=r"(a) : "l"(p));
    return a;
}
__device__ __forceinline__ void cp16(uint32_t saddr, const void* g) {
    asm volatile("cp.async.cg.shared.global [%0], [%1], 16;" :: "r"(saddr), "l"(g));
}
__device__ __forceinline__ float block_reduce_sum(float v, float* sbuf) {
    int tid = threadIdx.x;
    sbuf[tid] = v;
    __syncthreads();
    #pragma unroll
    for (int off = 128; off > 0; off >>= 1) {
        if (tid < off) sbuf[tid] += sbuf[tid + off];
        __syncthreads();
    }
    float r = sbuf[0];
    __syncthreads();
    return r;
}
__device__ __forceinline__ float block_reduce_sum512(float v, float* sbuf) {
    int tid = threadIdx.x;
    sbuf[tid] = v;
    __syncthreads();
    #pragma unroll
    for (int off = 256; off > 0; off >>= 1) {
        if (tid < off) sbuf[tid] += sbuf[tid + off];
        __syncthreads();
    }
    float r = sbuf[0];
    __syncthreads();
    return r;
}

// ------- W fp32 -> fp16 (scaled); last block computes ||b||^2 -------
#define WCONV_BLOCKS ((VO * DK / 4 + 255) / 256)
__global__ void __launch_bounds__(256) convW_bnorm_kernel(const float* __restrict__ W,
                                                          __half* __restrict__ dst,
                                                          const float* __restrict__ b) {
    if (blockIdx.x == WCONV_BLOCKS) {
        __shared__ float sbuf[256];
        float s = 0.f;
        for (int i = threadIdx.x; i < VO; i += 256) { float v = b[i]; s += v * v; }
        s = block_reduce_sum(s, sbuf);
        if (threadIdx.x == 0) g_y2 = s;
        return;
    }
    int i = blockIdx.x * 256 + threadIdx.x;
    if (i < VO * DK / 4) {
        float4 v = ((const float4*)W)[i];
        __half2 lo = __floats2half2_rn(v.x * WSCALE, v.y * WSCALE);
        __half2 hi = __floats2half2_rn(v.z * WSCALE, v.w * WSCALE);
        ((__half2*)dst)[2 * i]     = lo;
        ((__half2*)dst)[2 * i + 1] = hi;
    }
}

// ---- per-row: hidden->fp16 conversion, x_norm, p_copy, zero accumulators ----
__global__ void __launch_bounds__(256) row_prep_kernel(const float* __restrict__ hidden,
                                                       const float* __restrict__ Wc,
                                                       const float* __restrict__ bcp,
                                                       __half* __restrict__ hid_h) {
    __shared__ float s1[256];
    __shared__ float s2[256];
    int row = blockIdx.x;
    const float4* h4 = (const float4*)(hidden + (size_t)row * DK);
    const float4* w4 = (const float4*)Wc;
    int i = threadIdx.x;
    float4 h = h4[i];
    float4 w = w4[i];
    __half2 lo = __floats2half2_rn(h.x * HSCALE, h.y * HSCALE);
    __half2 hi = __floats2half2_rn(h.z * HSCALE, h.w * HSCALE);
    ((__half2*)(hid_h + (size_t)row * DK))[2 * i]     = lo;
    ((__half2*)(hid_h + (size_t)row * DK))[2 * i + 1] = hi;

    float ss = h.x * h.x + h.y * h.y + h.z * h.z + h.w * h.w;
    float sm = h.x * w.x + h.y * w.y + h.z * w.z + h.w * w.w;
    ss = block_reduce_sum(ss, s1);
    sm = block_reduce_sum(sm, s2);
    if (threadIdx.x == 0) {
        g_ss[row] = 0.f;
        g_db[row] = 0.f;
        float xn = fmaxf(sqrtf(ss), 1e-15f);
        g_xnorm[row] = xn;
        float art = atanhf(fminf(xn, 1.f - 1e-7f));
        float mn = fmaxf(fabsf(sm), 1e-15f);
        float t1 = tanhf(mn / xn * art) * (sm / mn);
        float bc = *bcp;
        float y2 = bc * bc, x2 = t1 * t1, xy = t1 * bc;
        float num = (1.f + 2.f * xy + y2) * t1 + (1.f - x2) * bc;
        float den = fmaxf(1.f + 2.f * xy + x2 * y2, 1e-15f);
        float u = num / den;
        float au = fmaxf(fabsf(u), 1e-15f);
        if (au > 0.996f) u = u / au * 0.996f;
        g_pcopy[row] = 1.f / (1.f + expf(-u));
    }
}

// ============ fp16 mma.sync GEMM (f16 accumulate): g_Mx = hidden @ W^T ============
#define BM 128
#define BN 128
#define BK 64
#define NSTG (DK / BK)          // 16
#define STAGE_BYTES 32768
#define SMEM_GEMM (2 * STAGE_BYTES)

__device__ __forceinline__ uint32_t sw128(uint32_t off) {
    return off ^ ((off >> 3) & 0x70);
}

__global__ void __launch_bounds__(256) gemm_mma_kernel(const float* __restrict__ bvec) {
    extern __shared__ char smem[];
    const uint32_t sb = smem_u32(smem);
    const int tid = threadIdx.x;
    const int wid = tid >> 5;
    const int lane = tid & 31;
    const int warp_m = wid & 1;
    const int warp_n = wid >> 1;
    const int row0 = blockIdx.y * BM;
    const int col0 = blockIdx.x * BN;

    const int lr = tid >> 3;
    const int lk = tid & 7;

    uint32_t acc[4][4][2];
    #pragma unroll
    for (int a = 0; a < 4; a++)
        #pragma unroll
        for (int b = 0; b < 4; b++) { acc[a][b][0] = 0u; acc[a][b][1] = 0u; }

    {
        const uint32_t abase = sb, bbase = sb + 16384;
        #pragma unroll
        for (int it = 0; it < 4; it++) {
            int r = lr + it * 32;
            uint32_t off = sw128(r * 128 + lk * 16);
            cp16(abase + off, g_hid_h + (size_t)(row0 + r) * DK + lk * 8);
            cp16(bbase + off, g_W_h + (size_t)(col0 + r) * DK + lk * 8);
        }
        asm volatile("cp.async.commit_group;" ::: "memory");
        asm volatile("cp.async.wait_group 0;" ::: "memory");
    }
    __syncthreads();

    for (int ks = 0; ks < NSTG; ks++) {
        if (ks + 1 < NSTG) {
            const uint32_t nb = sb + ((ks + 1) & 1) * STAGE_BYTES;
            const int k0 = (ks + 1) * BK;
            #pragma unroll
            for (int it = 0; it < 4; it++) {
                int r = lr + it * 32;
                uint32_t off = sw128(r * 128 + lk * 16);
                cp16(nb + off, g_hid_h + (size_t)(row0 + r) * DK + k0 + lk * 8);
                cp16(nb + 16384 + off, g_W_h + (size_t)(col0 + r) * DK + k0 + lk * 8);
            }
            asm volatile("cp.async.commit_group;" ::: "memory");
        }

        const uint32_t abase = sb + (ks & 1) * STAGE_BYTES;
        const uint32_t bbase = abase + 16384;
        #pragma unroll
        for (int kk = 0; kk < 4; kk++) {
            uint32_t afr[4][4];
            uint32_t bfr[4][2];
            #pragma unroll
            for (int mf = 0; mf < 4; mf++) {
                int r = warp_m * 64 + mf * 16 + (lane & 15);
                uint32_t off = sw128(r * 128 + kk * 32 + ((lane >> 4) & 1) * 16);
                asm volatile("ldmatrix.sync.aligned.m8n8.x4.shared.b16 {%0,%1,%2,%3}, [%4];"
                             : "=r"(afr[mf][0]), "=r"(afr[mf][1]),
                               "=r"(afr[mf][2]), "=r"(afr[mf][3])
                             : "r"(abase + off));
            }
            #pragma unroll
            for (int nh = 0; nh < 2; nh++) {
                int r = warp_n * 32 + nh * 16 + ((lane >> 4) & 1) * 8 + (lane & 7);
                uint32_t off = sw128(r * 128 + kk * 32 + ((lane >> 3) & 1) * 16);
                asm volatile("ldmatrix.sync.aligned.m8n8.x4.shared.b16 {%0,%1,%2,%3}, [%4];"
                             : "=r"(bfr[nh * 2][0]), "=r"(bfr[nh * 2][1]),
                               "=r"(bfr[nh * 2 + 1][0]), "=r"(bfr[nh * 2 + 1][1])
                             : "r"(bbase + off));
            }
            #pragma unroll
            for (int mf = 0; mf < 4; mf++)
                #pragma unroll
                for (int nf = 0; nf < 4; nf++) {
                    asm volatile(
                        "mma.sync.aligned.m16n8k16.row.col.f16.f16.f16.f16 "
                        "{%0,%1}, {%2,%3,%4,%5}, {%6,%7}, {%0,%1};"
                        : "+r"(acc[mf][nf][0]), "+r"(acc[mf][nf][1])
                        : "r"(afr[mf][0]), "r"(afr[mf][1]),
                          "r"(afr[mf][2]), "r"(afr[mf][3]),
                          "r"(bfr[nf][0]), "r"(bfr[nf][1]));
                }
        }
        if (ks + 1 < NSTG)
            asm volatile("cp.async.wait_group 0;" ::: "memory");
        __syncthreads();
    }

    // ---- epilogue: descale, write Mx bf16, fused ss/db row reductions ----
    float bb[4][2];
    #pragma unroll
    for (int nf = 0; nf < 4; nf++) {
        int c = col0 + warp_n * 32 + nf * 8 + (lane & 3) * 2;
        float2 v = *(const float2*)(bvec + c);
        bb[nf][0] = v.x; bb[nf][1] = v.y;
    }
    #pragma unroll
    for (int mf = 0; mf < 4; mf++) {
        #pragma unroll
        for (int hf = 0; hf < 2; hf++) {
            int row = row0 + warp_m * 64 + mf * 16 + (lane >> 2) + hf * 8;
            __nv_bfloat16* orow = g_Mx + (size_t)row * VO + col0 + warp_n * 32 + (lane & 3) * 2;
            float ss = 0.f, db = 0.f;
            #pragma unroll
            for (int nf = 0; nf < 4; nf++) {
                float2 cv = __half22float2(*(__half2*)&acc[mf][nf][hf]);
                float c0 = cv.x * DESCALE;
                float c1 = cv.y * DESCALE;
                ss += c0 * c0 + c1 * c1;
                db += c0 * bb[nf][0] + c1 * bb[nf][1];
                *(__nv_bfloat162*)(orow + nf * 8) = __floats2bfloat162_rn(c0, c1);
            }
            ss += __shfl_xor_sync(0xffffffff, ss, 1);
            ss += __shfl_xor_sync(0xffffffff, ss, 2);
            db += __shfl_xor_sync(0xffffffff, db, 1);
            db += __shfl_xor_sync(0xffffffff, db, 2);
            if ((lane & 3) == 0) {
                atomicAdd(&g_ss[row], ss);
                atomicAdd(&g_db[row], db);
            }
        }
    }
}

// ====== fused output: scalar chain + exact softmax (no max needed: |l|<=0.996) ======
// 512 threads/block; pass 1 overwrites the smem Mx cache with bf16 exp(l) (pad zeroed),
// pass 2 is a pure scale-and-store.
__global__ void __launch_bounds__(512) fused_out_kernel(const float* __restrict__ b,
                                                        const int* __restrict__ padp,
                                                        float* __restrict__ out) {
    extern __shared__ char smraw[];
    __nv_bfloat162* smx = (__nv_bfloat162*)smraw;
    __shared__ float rbuf[512];
    __shared__ float sc_g, sc_d, sc_inv0;

    const int row = blockIdx.x;
    const int tid = threadIdx.x;
    const int pad = *padp;

    // cache Mx row (VO bf16 = 4000 uint4)
    const uint4* src = (const uint4*)(g_Mx + (size_t)row * VO);
    uint4* dst = (uint4*)smraw;
    #pragma unroll 2
    for (int i = tid; i < VO / 8; i += 512) dst[i] = src[i];

    if (tid == 0) {
        float ss = g_ss[row];
        float db = g_db[row];
        float xn = g_xnorm[row];
        float mxn = fmaxf(sqrtf(ss), 1e-15f);
        float art = atanhf(fminf(xn, 1.f - 1e-7f));
        float t = tanhf(mxn / xn * art);
        float alpha = t / mxn;
        float xy = alpha * db;
        float x2 = t * t;
        float y2 = g_y2;
        float Ac = 1.f + 2.f * xy + y2;
        float Bc = 1.f - x2;
        float den = fmaxf(1.f + 2.f * xy + x2 * y2, 1e-15f);
        float nl2 = (Ac * Ac * t * t + 2.f * Ac * Bc * alpha * db + Bc * Bc * y2) / (den * den);
        float nl = fmaxf(sqrtf(nl2), 1e-15f);
        float sc = (nl > 0.996f) ? (0.996f / nl) : 1.f;
        sc_g = sc * Ac * alpha / den;
        sc_d = sc * Bc / den;
        sc_inv0 = 1.f - g_pcopy[row];
    }
    __syncthreads();

    const float gamma = sc_g, delta = sc_d;
    const float2* b2 = (const float2*)b;

    // pass 1: exp + sum; overwrite smem with bf16 exp values (pad already zeroed)
    float s = 0.f;
    for (int i = tid; i < VO / 2; i += 512) {
        __nv_bfloat162 m = smx[i];
        float2 bv = b2[i];
        float l0 = gamma * __bfloat162float(m.x) + delta * bv.x;
        float l1 = gamma * __bfloat162float(m.y) + delta * bv.y;
        float e0 = __expf(l0);
        float e1 = __expf(l1);
        int base = i * 2;
        if (pad == base) e0 = 0.f;
        if (pad == base + 1) e1 = 0.f;
        s += e0 + e1;
        smx[i] = __floats2bfloat162_rn(e0, e1);
    }
    s = block_reduce_sum512(s, rbuf);
    const float inv = sc_inv0 / s;

    // pass 2: scale-and-store
    float2* o2 = (float2*)(out + (size_t)row * OC);
    for (int i = tid; i < VO / 2; i += 512) {
        __nv_bfloat162 e = smx[i];
        float2 r;
        r.x = __bfloat162float(e.x) * inv;
        r.y = __bfloat162float(e.y) * inv;
        o2[i] = r;
    }
}

// ------- copy branch: per-batch (64x512)@(512x500) small GEMM (full fp32) -------
#define SCH 32
__global__ void __launch_bounds__(256) copy_kernel(const float* __restrict__ attn,
                                                   const float* __restrict__ src,
                                                   float* __restrict__ out) {
    __shared__ float sa[64][SCH + 1];
    __shared__ float sbuf[SCH][128];
    __shared__ float spc[64];
    const int bb = blockIdx.y;
    const int c0 = blockIdx.x * 128;
    const int tid = threadIdx.x;
    const int tx = tid % 16;
    const int ty = tid / 16;

    if (tid < 64) spc[tid] = g_pcopy[tid * NB + bb];

    float acc[4][8] = {};
    for (int s0 = 0; s0 < SL; s0 += SCH) {
        __syncthreads();
        for (int i = tid; i < 64 * (SCH / 4); i += 256) {
            int t = i / (SCH / 4);
            int sv = i % (SCH / 4);
            float4 v = *(const float4*)(attn + (size_t)(t * NB + bb) * SL + s0 + sv * 4);
            float pc = spc[t];
            sa[t][sv * 4 + 0] = v.x * pc;
            sa[t][sv * 4 + 1] = v.y * pc;
            sa[t][sv * 4 + 2] = v.z * pc;
            sa[t][sv * 4 + 3] = v.w * pc;
        }
        for (int i = tid; i < SCH * 128; i += 256) {
            int s = i / 128;
            int c = i % 128;
            int cg = c0 + c;
            sbuf[s][c] = (cg < CV) ? src[(size_t)(s0 + s) * (NB * CV) + bb * CV + cg] : 0.f;
        }
        __syncthreads();
        #pragma unroll 8
        for (int s = 0; s < SCH; s++) {
            float a[4], bf[8];
            #pragma unroll
            for (int i = 0; i < 4; i++) a[i] = sa[ty * 4 + i][s];
            #pragma unroll
            for (int j = 0; j < 8; j++) bf[j] = sbuf[s][tx * 8 + j];
            #pragma unroll
            for (int i = 0; i < 4; i++)
                #pragma unroll
                for (int j = 0; j < 8; j++)
                    acc[i][j] = fmaf(a[i], bf[j], acc[i][j]);
        }
    }
    #pragma unroll
    for (int i = 0; i < 4; i++) {
        int t = ty * 4 + i;
        #pragma unroll
        for (int j = 0; j < 8; j++) {
            int c = c0 + tx * 8 + j;
            if (c < CV)
                out[(size_t)(t * NB + bb) * OC + VO + c] = acc[i][j];
        }
    }
}

// ---------------- launch ----------------
extern "C" void kernel_launch(void* const* d_in, const int* in_sizes, int n_in,
                              void* d_out, int out_size) {
    const float* hidden = (const float*)d_in[0];
    const float* attn   = (const float*)d_in[1];
    const float* srcm   = (const float*)d_in[2];
    const float* W      = (const float*)d_in[3];
    const float* b      = (const float*)d_in[4];
    const float* Wc     = (const float*)d_in[5];
    const float* bc     = (const float*)d_in[6];
    const int*   pad    = (const int*)d_in[7];
    float* out = (float*)d_out;

    cudaFuncSetAttribute(gemm_mma_kernel,
                         cudaFuncAttributeMaxDynamicSharedMemorySize, SMEM_GEMM);
    cudaFuncSetAttribute(fused_out_kernel,
                         cudaFuncAttributeMaxDynamicSharedMemorySize, VO * 2);

    __half* hid_h;
    __half* W_h;
    cudaGetSymbolAddress((void**)&hid_h, g_hid_h);
    cudaGetSymbolAddress((void**)&W_h, g_W_h);

    convW_bnorm_kernel<<<WCONV_BLOCKS + 1, 256>>>(W, W_h, b);
    row_prep_kernel<<<NR, 256>>>(hidden, Wc, bc, hid_h);
    gemm_mma_kernel<<<dim3(VO / BN, NR / BM), 256, SMEM_GEMM>>>(b);
    fused_out_kernel<<<NR, 512, VO * 2>>>(b, pad, out);
    copy_kernel<<<dim3((CV + 127) / 128, NB), 256>>>(attn, srcm, out);
}